// round 14
// baseline (speedup 1.0000x reference)
#include <cuda_runtime.h>

#define HH 180
#define WW 180
#define BB 8
#define NF 24
#define IMG (HH*WW)            // 32400
#define TOT (BB*IMG)           // 259200

#define TX 60
#define TY 12
#define SH (TY+4)              // 16 S-region rows
#define SWP 68                 // padded S width (logical 64)
#define UW 68                  // u-region width (TX+8)
#define UH (TY+8)              // 20
#define NUP (UW*UH)            // 1360
#define NSB (SH*SWP)           // 1088 floats per S buffer
#define NT 256
#define NBLK (3*15*BB)         // 360 blocks (single wave at occ 3)

#define LUTN 2048
#define XMIN (-2.0f)
#define LUT_SCALE 512.0f       // LUTN/4
#define NLB 4                  // LUT builder blocks
#define LCHUNK 513             // ceil((LUTN+1)/NLB)
#define QSCALE 1048576.0f      // 2^20 fixed-point for deterministic sum
#define SPIN_MAX 65536         // bounded spin -> fallback (deadlock-proof)

__device__ float2 g_lut2[LUTN];
__device__ unsigned long long g_sum = 0ull;
__device__ int g_lutcnt = 0;
__device__ int g_cnt = 0;
__device__ int g_exit = 0;

// ----------------------------------------------------------- fused mega-kernel
__global__ __launch_bounds__(NT, 3)
void tnrd_kernel(const float* __restrict__ u,
                 const float* __restrict__ f,
                 const float* __restrict__ filters,
                 const float* __restrict__ lam_p,
                 const float* __restrict__ mu,
                 const float* __restrict__ w,
                 float* __restrict__ out) {
    __shared__ float  su[NUP];             // u with halo-4        (5440 B)
    __shared__ float  sS[4][NSB];          // 4 scaled_phi buffers (17408 B)
    __shared__ float2 slut[LUTN];          //                      (16384 B)
    __shared__ float  sfiltR[NF * 5 * 8];  // row-padded filters   (3840 B)
    __shared__ float  wred[8];
    __shared__ float  sinvM;
    __shared__ int    sflag;

    const int tid = threadIdx.x;
    const int x0 = blockIdx.x * TX;
    const int y0 = blockIdx.y * TY;
    const int b  = blockIdx.z;
    const int flat = blockIdx.x + 3 * blockIdx.y + 45 * blockIdx.z;
    const float* ub = u + b * IMG;

    // ---- LUT build: 4 designated blocks compute quarters into global ----
    if (flat < NLB) {
        int lo = flat * LCHUNK;
        int hi = lo + LCHUNK;
        if (hi > LUTN + 1) hi = LUTN + 1;
        for (int i = lo + tid; i < hi; i += NT) {
            float x = XMIN + (float)i * (4.0f / (float)LUTN);
            float s = 0.0f;
            #pragma unroll 1
            for (int j = 0; j < 31; j++) {
                float d = x - mu[j];
                s += w[j] * expf(-d * d * 50.0f);   // 1/(2*0.1^2) = 50
            }
            if (i < LUTN) *((volatile float*)&g_lut2[i].x) = s;
            if (i > 0)    *((volatile float*)&g_lut2[i - 1].y) = s;
        }
        __syncthreads();
        if (tid == 0) {
            __threadfence();
            atomicAdd(&g_lutcnt, 1);
        }
    }

    // ---- filters to shared ----
    for (int i = tid; i < NF * 5 * 8; i += NT) {
        int kr = i >> 3, x = i & 7;       // kr = k*5+row
        sfiltR[i] = (x < 5) ? filters[kr * 5 + x] : 0.0f;
    }

    // ---- load u (halo 4) + this tile's weighted interior sum ----
    float rsum = 0.0f;
    for (int i = tid; i < NUP; i += NT) {
        int uy = i / UW, ux = i - uy * UW;
        int gy = y0 + uy - 4, gx = x0 + ux - 4;
        float v = 0.0f;
        if (gy >= 0 && gy < HH && gx >= 0 && gx < WW) v = ub[gy * WW + gx];
        su[i] = v;
        if (uy >= 4 && uy < 4 + TY && ux >= 4 && ux < 4 + TX) {
            float cy = (gy == 0 || gy == HH - 1) ? 2.0f : 3.0f;
            float cx = (gx == 0 || gx == WW - 1) ? 2.0f : 3.0f;
            rsum += v * (cy * cx);
        }
    }
    #pragma unroll
    for (int st = 16; st > 0; st >>= 1)
        rsum += __shfl_xor_sync(0xffffffffu, rsum, st);
    if ((tid & 31) == 0) wred[tid >> 5] = rsum;
    __syncthreads();
    if (tid == 0) {
        float s = 0.0f;
        #pragma unroll
        for (int q = 0; q < 8; q++) s += wred[q];
        unsigned long long qv = (unsigned long long)llrintf(s * QSCALE);
        atomicAdd(&g_sum, qv);
        __threadfence();
        atomicAdd(&g_cnt, 1);
        // bounded wait for LUT (normal case: already done)
        int it = 0;
        while (*(volatile int*)&g_lutcnt < NLB && it < SPIN_MAX) {
            __nanosleep(32); it++;
        }
        sflag = (*(volatile int*)&g_lutcnt >= NLB) ? 1 : 0;
        __threadfence();
    }
    __syncthreads();

    if (sflag) {
        // copy LUT global -> shared (L2-hot)
        const float4* gl = (const float4*)g_lut2;   // 1024 float4
        float4* sl = (float4*)slut;
        for (int i = tid; i < LUTN / 2; i += NT) sl[i] = gl[i];
    } else {
        // fallback: build LUT locally (deadlock-proof path)
        for (int i = tid; i <= LUTN; i += NT) {
            float x = XMIN + (float)i * (4.0f / (float)LUTN);
            float s = 0.0f;
            #pragma unroll 1
            for (int j = 0; j < 31; j++) {
                float d = x - mu[j];
                s += w[j] * expf(-d * d * 50.0f);
            }
            if (i < LUTN) slut[i].x = s;
            if (i > 0)    slut[i - 1].y = s;
        }
    }
    __syncthreads();

    // ---- per-thread S-strip: sy in 0..15, 4 consecutive x at sxq ----
    const int sy  = tid >> 4;
    const int sxq = (tid & 15) << 2;

    // register-resident 5x8 u window (constant across all k)
    float sur[5][8];
    #pragma unroll
    for (int r = 0; r < 5; r++) {
        float4 a = *(const float4*)&su[(sy + r) * UW + sxq];
        float4 c = *(const float4*)&su[(sy + r) * UW + sxq + 4];
        sur[r][0] = a.x; sur[r][1] = a.y; sur[r][2] = a.z; sur[r][3] = a.w;
        sur[r][4] = c.x; sur[r][5] = c.y; sur[r][6] = c.z; sur[r][7] = c.w;
    }

    // u_sigma for the 4 S-points, premultiplied by border mask
    float susigm[4];
    {
        float colsum[6];
        #pragma unroll
        for (int c = 0; c < 6; c++)
            colsum[c] = sur[1][c + 1] + sur[2][c + 1] + sur[3][c + 1];
        #pragma unroll
        for (int j = 0; j < 4; j++) {
            float s = (colsum[j] + colsum[j + 1] + colsum[j + 2]) * (1.0f / 9.0f);
            int iy = y0 + sy - 2, ix = x0 + sxq + j - 2;
            if (iy < 0 || iy >= HH || ix < 0 || ix >= WW) s = 0.0f;
            susigm[j] = s;
        }
    }

    // output strip mapping (180 4-wide strips over 256 threads)
    const int oy  = tid / 15;
    const int oxq = (tid - oy * 15) * 4;
    const bool has_out = (tid < TY * 15);

    float acc[4] = {0.0f, 0.0f, 0.0f, 0.0f};

    // ===== software-pipelined pair loop =====
    auto conv_pair = [&](int pp, float cvo[2][4]) {
        #pragma unroll
        for (int kk = 0; kk < 2; kk++) {
            const int k = 2 * pp + kk;
            #pragma unroll
            for (int j = 0; j < 4; j++) cvo[kk][j] = 0.0f;
            #pragma unroll
            for (int ry = 0; ry < 5; ry++) {
                const float* fr = &sfiltR[(k * 5 + ry) * 8];
                float4 fa = *(const float4*)fr;
                float  fe = fr[4];
                float fv;
                #pragma unroll
                for (int rx = 0; rx < 5; rx++) {
                    fv = (rx == 0) ? fa.x : (rx == 1) ? fa.y :
                         (rx == 2) ? fa.z : (rx == 3) ? fa.w : fe;
                    #pragma unroll
                    for (int j = 0; j < 4; j++)
                        cvo[kk][j] += fv * sur[ry][j + rx];
                }
            }
        }
    };
    auto lut_store = [&](int pp, float cvi[2][4]) {
        const int base = ((pp & 1) << 1);
        #pragma unroll
        for (int kk = 0; kk < 2; kk++) {
            float4 v;
            #pragma unroll
            for (int j = 0; j < 4; j++) {
                float xc = fminf(fmaxf(cvi[kk][j], XMIN), 2.0f);
                float t = (xc - XMIN) * LUT_SCALE;
                int idx = (int)t;
                idx = idx > (LUTN - 1) ? (LUTN - 1) : idx;
                float frac = t - (float)idx;
                float2 L = slut[idx];
                float phi = L.x + frac * (L.y - L.x);
                ((float*)&v)[j] = susigm[j] * phi;
            }
            *(float4*)&sS[base + kk][sy * SWP + sxq] = v;
        }
    };

    // prologue: pair 0
    {
        float cv0[2][4];
        conv_pair(0, cv0);
        lut_store(0, cv0);
    }
    __syncthreads();

    #pragma unroll 1
    for (int p = 0; p < NF / 2; p++) {
        const int bb = (p & 1) << 1;      // buffers being consumed

        // staged conv for next pair (independent FFMA to hide phase-2 LDS)
        float cvn[2][4];
        if (p < NF / 2 - 1) conv_pair(p + 1, cvn);

        // phase 2: transposed conv for both filters of pair p
        if (has_out) {
            #pragma unroll
            for (int kk = 0; kk < 2; kk++) {
                const int k = 2 * p + kk;
                const float* Sb = sS[bb + kk];
                #pragma unroll
                for (int rr = 0; rr < 5; rr++) {
                    float tr[8];
                    float4 a = *(const float4*)&Sb[(oy + rr) * SWP + oxq];
                    float4 c = *(const float4*)&Sb[(oy + rr) * SWP + oxq + 4];
                    tr[0] = a.x; tr[1] = a.y; tr[2] = a.z; tr[3] = a.w;
                    tr[4] = c.x; tr[5] = c.y; tr[6] = c.z; tr[7] = c.w;
                    const float* fr = &sfiltR[(k * 5 + (4 - rr)) * 8];
                    float4 fa = *(const float4*)fr;
                    float  fe = fr[4];
                    float fv;
                    #pragma unroll
                    for (int rx = 0; rx < 5; rx++) {
                        fv = (rx == 0) ? fa.x : (rx == 1) ? fa.y : (rx == 2) ? fa.z
                           : (rx == 3) ? fa.w : fe;
                        #pragma unroll
                        for (int j = 0; j < 4; j++)
                            acc[j] += fv * tr[j + 4 - rx];
                    }
                }
            }
        }

        // publish next pair into the other buffer set
        if (p < NF / 2 - 1) lut_store(p + 1, cvn);
        __syncthreads();
    }

    // ---- obtain global M: bounded wait, else direct fallback sum ----
    if (tid == 0) {
        int it = 0;
        while (*(volatile int*)&g_cnt < NBLK && it < SPIN_MAX) {
            __nanosleep(64); it++;
        }
        if (*(volatile int*)&g_cnt >= NBLK) {
            __threadfence();
            unsigned long long qv = *(volatile unsigned long long*)&g_sum;
            float s = (float)qv * (1.0f / QSCALE);
            float M = s * (1.0f / (9.0f * (float)TOT)) + 0.001f;
            sinvM = 1.0f / M;
            sflag = 1;
        } else {
            sflag = 0;
        }
    }
    __syncthreads();
    if (!sflag) {
        // fallback: compute the global weighted sum directly (L2-hot u)
        float rs = 0.0f;
        for (int i = tid; i < TOT; i += NT) {
            int pix = i % IMG;
            int y = pix / WW;
            int x = pix - y * WW;
            float cy = (y == 0 || y == HH - 1) ? 2.0f : 3.0f;
            float cx = (x == 0 || x == WW - 1) ? 2.0f : 3.0f;
            rs += u[i] * (cy * cx);
        }
        #pragma unroll
        for (int st = 16; st > 0; st >>= 1)
            rs += __shfl_xor_sync(0xffffffffu, rs, st);
        if ((tid & 31) == 0) wred[tid >> 5] = rs;
        __syncthreads();
        if (tid == 0) {
            float s = 0.0f;
            #pragma unroll
            for (int q = 0; q < 8; q++) s += wred[q];
            float M = s * (1.0f / (9.0f * (float)TOT)) + 0.001f;
            sinvM = 1.0f / M;
        }
        __syncthreads();
    }
    if (tid == 0) {
        int e = atomicAdd(&g_exit, 1);
        if (e == NBLK - 1) {               // last block resets for graph replay
            g_sum = 0ull;
            g_cnt = 0;
            g_lutcnt = 0;
            __threadfence();
            g_exit = 0;
        }
    }

    if (has_out) {
        const float invM = sinvM;
        const float lam  = lam_p[0];
        int iy = y0 + oy, ixb = x0 + oxq;
        float4 fv4 = *(const float4*)&f[b * IMG + iy * WW + ixb];
        float4 uv4 = *(const float4*)&su[(oy + 4) * UW + oxq + 4];
        float4 o4;
        #pragma unroll
        for (int j = 0; j < 4; j++) {
            float uv = ((const float*)&uv4)[j];
            float fv = ((const float*)&fv4)[j];
            float reac = lam * (uv - fv) / (uv * uv + 1e-3f);
            float o = uv - acc[j] * invM - reac;
            ((float*)&o4)[j] = fminf(fmaxf(o, 0.0f), 1.0f);
        }
        *(float4*)&out[b * IMG + iy * WW + ixb] = o4;
    }
}

// ------------------------------------------------------------------- launch
extern "C" void kernel_launch(void* const* d_in, const int* in_sizes, int n_in,
                              void* d_out, int out_size) {
    const float* u       = (const float*)d_in[0];
    const float* f       = (const float*)d_in[1];
    const float* filters = (const float*)d_in[2];
    const float* lam     = (const float*)d_in[3];
    const float* mu      = (const float*)d_in[4];
    const float* w       = (const float*)d_in[5];
    float* out = (float*)d_out;

    dim3 grid(WW / TX, HH / TY, BB);   // 3 x 15 x 8 = 360 blocks
    tnrd_kernel<<<grid, NT>>>(u, f, filters, lam, mu, w, out);
}

// round 16
// speedup vs baseline: 1.0544x; 1.0544x over previous
#include <cuda_runtime.h>

#define HH 180
#define WW 180
#define BB 8
#define NF 24
#define IMG (HH*WW)            // 32400
#define TOT (BB*IMG)           // 259200

#define TX 60
#define TY 12
#define SH (TY+4)              // 16 S-region rows
#define SWP 68                 // padded S width (logical 64)
#define UW 68                  // u-region width (TX+8)
#define UH (TY+8)              // 20
#define NUP (UW*UH)            // 1360
#define NSB (SH*SWP)           // 1088 floats per S buffer
#define NT 256
#define NBLK (3*15*BB)         // 360 blocks (single wave at occ 3)

#define LUTN 512
#define XMIN (-2.0f)
#define LUT_SCALE 128.0f       // LUTN/4
#define QSCALE 1048576.0f      // 2^20 fixed-point for deterministic sum
#define SPIN_MAX 65536         // bounded spin -> fallback (deadlock-proof)

__device__ unsigned long long g_sum = 0ull;
__device__ int g_cnt = 0;
__device__ int g_exit = 0;

// ----------------------------------------------------------- fused mega-kernel
__global__ __launch_bounds__(NT, 3)
void tnrd_kernel(const float* __restrict__ u,
                 const float* __restrict__ f,
                 const float* __restrict__ filters,
                 const float* __restrict__ lam_p,
                 const float* __restrict__ mu,
                 const float* __restrict__ w,
                 float* __restrict__ out) {
    __shared__ __align__(16) float  su[NUP];             // u with halo-4  (5440 B)
    __shared__ __align__(16) float  sS[4][NSB];          // 4 S buffers    (17408 B)
    __shared__ __align__(16) float2 slut[LUTN + 2];      // 514 pairs      (4112 B)
    __shared__ __align__(16) float  sfiltR[NF * 5 * 8];  // filters        (3840 B)
    __shared__ float  smu[31], sw[31];
    __shared__ float  wred[8];
    __shared__ float  sinvM;
    __shared__ int    sflag;

    const int tid = threadIdx.x;
    const int x0 = blockIdx.x * TX;
    const int y0 = blockIdx.y * TY;
    const int b  = blockIdx.z;
    const float* ub = u + b * IMG;

    // ---- stage small params to shared ----
    if (tid < 31) {
        smu[tid] = mu[tid];
        sw[tid]  = w[tid];
    }
    for (int i = tid; i < NF * 5 * 8; i += NT) {
        int kr = i >> 3, x = i & 7;       // kr = k*5+row
        sfiltR[i] = (x < 5) ? filters[kr * 5 + x] : 0.0f;
    }

    // ---- load u (halo 4) + this tile's weighted interior sum ----
    float rsum = 0.0f;
    for (int i = tid; i < NUP; i += NT) {
        int uy = i / UW, ux = i - uy * UW;
        int gy = y0 + uy - 4, gx = x0 + ux - 4;
        float v = 0.0f;
        if (gy >= 0 && gy < HH && gx >= 0 && gx < WW) v = ub[gy * WW + gx];
        su[i] = v;
        if (uy >= 4 && uy < 4 + TY && ux >= 4 && ux < 4 + TX) {
            float cy = (gy == 0 || gy == HH - 1) ? 2.0f : 3.0f;
            float cx = (gx == 0 || gx == WW - 1) ? 2.0f : 3.0f;
            rsum += v * (cy * cx);
        }
    }
    #pragma unroll
    for (int st = 16; st > 0; st >>= 1)
        rsum += __shfl_xor_sync(0xffffffffu, rsum, st);
    if ((tid & 31) == 0) wred[tid >> 5] = rsum;
    __syncthreads();                       // covers su, sfiltR, smu/sw, wred

    if (tid == 0) {
        float s = 0.0f;
        #pragma unroll
        for (int q = 0; q < 8; q++) s += wred[q];
        unsigned long long qv = (unsigned long long)llrintf(s * QSCALE);
        atomicAdd(&g_sum, qv);
        __threadfence();
        atomicAdd(&g_cnt, 1);
    }

    // ---- local LUT build (513 pair entries need phi at 514 points) ----
    for (int i = tid; i <= LUTN + 1; i += NT) {
        float x = XMIN + (float)i * (4.0f / (float)LUTN);
        float s = 0.0f;
        #pragma unroll 1
        for (int j = 0; j < 31; j++) {
            float d = x - smu[j];
            s += sw[j] * __expf(-d * d * 50.0f);   // 1/(2*0.1^2) = 50
        }
        if (i <= LUTN) slut[i].x = s;
        if (i > 0)     slut[i - 1].y = s;
    }

    // ---- per-thread S-strip: sy in 0..15, 4 consecutive x at sxq ----
    const int sy  = tid >> 4;
    const int sxq = (tid & 15) << 2;

    // register-resident 5x8 u window (constant across all k)
    float sur[5][8];
    #pragma unroll
    for (int r = 0; r < 5; r++) {
        float4 a = *(const float4*)&su[(sy + r) * UW + sxq];
        float4 c = *(const float4*)&su[(sy + r) * UW + sxq + 4];
        sur[r][0] = a.x; sur[r][1] = a.y; sur[r][2] = a.z; sur[r][3] = a.w;
        sur[r][4] = c.x; sur[r][5] = c.y; sur[r][6] = c.z; sur[r][7] = c.w;
    }

    // u_sigma for the 4 S-points, premultiplied by border mask
    float susigm[4];
    {
        float colsum[6];
        #pragma unroll
        for (int c = 0; c < 6; c++)
            colsum[c] = sur[1][c + 1] + sur[2][c + 1] + sur[3][c + 1];
        #pragma unroll
        for (int j = 0; j < 4; j++) {
            float s = (colsum[j] + colsum[j + 1] + colsum[j + 2]) * (1.0f / 9.0f);
            int iy = y0 + sy - 2, ix = x0 + sxq + j - 2;
            if (iy < 0 || iy >= HH || ix < 0 || ix >= WW) s = 0.0f;
            susigm[j] = s;
        }
    }

    // output strip mapping (180 4-wide strips over 256 threads)
    const int oy  = tid / 15;
    const int oxq = (tid - oy * 15) * 4;
    const bool has_out = (tid < TY * 15);

    float acc[4] = {0.0f, 0.0f, 0.0f, 0.0f};

    __syncthreads();                       // LUT visible to all

    #pragma unroll 1
    for (int p = 0; p < NF / 2; p++) {
        const int bb = (p & 1) << 1;      // buffer base: 0 or 2

        // phase 1: conv + LUT for filters 2p and 2p+1 (all 256 threads)
        #pragma unroll
        for (int kk = 0; kk < 2; kk++) {
            const int k = 2 * p + kk;
            float cv[4] = {0.0f, 0.0f, 0.0f, 0.0f};
            #pragma unroll
            for (int ry = 0; ry < 5; ry++) {
                const float* fr = &sfiltR[(k * 5 + ry) * 8];
                float4 fa = *(const float4*)fr;
                float  fe = fr[4];
                float fv;
                #pragma unroll
                for (int rx = 0; rx < 5; rx++) {
                    fv = (rx == 0) ? fa.x : (rx == 1) ? fa.y : (rx == 2) ? fa.z
                       : (rx == 3) ? fa.w : fe;
                    #pragma unroll
                    for (int j = 0; j < 4; j++)
                        cv[j] += fv * sur[ry][j + rx];
                }
            }
            float4 v;
            #pragma unroll
            for (int j = 0; j < 4; j++) {
                float xc = fminf(fmaxf(cv[j], XMIN), 2.0f);
                float t = (xc - XMIN) * LUT_SCALE;    // [0, 512]
                int idx = (int)t;                     // 0..512, no clamp needed
                float frac = t - (float)idx;
                float2 L = slut[idx];
                float phi = L.x + frac * (L.y - L.x);
                ((float*)&v)[j] = susigm[j] * phi;
            }
            *(float4*)&sS[bb + kk][sy * SWP + sxq] = v;
        }
        __syncthreads();

        // phase 2: transposed conv for both filters of the pair
        if (has_out) {
            #pragma unroll
            for (int kk = 0; kk < 2; kk++) {
                const int k = 2 * p + kk;
                const float* Sb = sS[bb + kk];
                #pragma unroll
                for (int rr = 0; rr < 5; rr++) {
                    float tr[8];
                    float4 a = *(const float4*)&Sb[(oy + rr) * SWP + oxq];
                    float4 c = *(const float4*)&Sb[(oy + rr) * SWP + oxq + 4];
                    tr[0] = a.x; tr[1] = a.y; tr[2] = a.z; tr[3] = a.w;
                    tr[4] = c.x; tr[5] = c.y; tr[6] = c.z; tr[7] = c.w;
                    const float* fr = &sfiltR[(k * 5 + (4 - rr)) * 8];
                    float4 fa = *(const float4*)fr;
                    float  fe = fr[4];
                    float fv;
                    #pragma unroll
                    for (int rx = 0; rx < 5; rx++) {
                        fv = (rx == 0) ? fa.x : (rx == 1) ? fa.y : (rx == 2) ? fa.z
                           : (rx == 3) ? fa.w : fe;
                        #pragma unroll
                        for (int j = 0; j < 4; j++)
                            acc[j] += fv * tr[j + 4 - rx];
                    }
                }
            }
        }
        __syncthreads();
    }

    // ---- obtain global M: bounded wait, else direct fallback sum ----
    if (tid == 0) {
        int it = 0;
        while (*(volatile int*)&g_cnt < NBLK && it < SPIN_MAX) {
            __nanosleep(64); it++;
        }
        if (*(volatile int*)&g_cnt >= NBLK) {
            __threadfence();
            unsigned long long qv = *(volatile unsigned long long*)&g_sum;
            float s = (float)qv * (1.0f / QSCALE);
            float M = s * (1.0f / (9.0f * (float)TOT)) + 0.001f;
            sinvM = 1.0f / M;
            sflag = 1;
        } else {
            sflag = 0;
        }
    }
    __syncthreads();
    if (!sflag) {
        // fallback: compute the global weighted sum directly (L2-hot u)
        float rs = 0.0f;
        for (int i = tid; i < TOT; i += NT) {
            int pix = i % IMG;
            int y = pix / WW;
            int x = pix - y * WW;
            float cy = (y == 0 || y == HH - 1) ? 2.0f : 3.0f;
            float cx = (x == 0 || x == WW - 1) ? 2.0f : 3.0f;
            rs += u[i] * (cy * cx);
        }
        #pragma unroll
        for (int st = 16; st > 0; st >>= 1)
            rs += __shfl_xor_sync(0xffffffffu, rs, st);
        if ((tid & 31) == 0) wred[tid >> 5] = rs;
        __syncthreads();
        if (tid == 0) {
            float s = 0.0f;
            #pragma unroll
            for (int q = 0; q < 8; q++) s += wred[q];
            float M = s * (1.0f / (9.0f * (float)TOT)) + 0.001f;
            sinvM = 1.0f / M;
        }
        __syncthreads();
    }
    if (tid == 0) {
        int e = atomicAdd(&g_exit, 1);
        if (e == NBLK - 1) {               // last block resets for graph replay
            g_sum = 0ull;
            g_cnt = 0;
            __threadfence();
            g_exit = 0;
        }
    }

    if (has_out) {
        const float invM = sinvM;
        const float lam  = lam_p[0];
        int iy = y0 + oy, ixb = x0 + oxq;
        float4 fv4 = *(const float4*)&f[b * IMG + iy * WW + ixb];
        float4 uv4 = *(const float4*)&su[(oy + 4) * UW + oxq + 4];
        float4 o4;
        #pragma unroll
        for (int j = 0; j < 4; j++) {
            float uv = ((const float*)&uv4)[j];
            float fv = ((const float*)&fv4)[j];
            float reac = lam * (uv - fv) / (uv * uv + 1e-3f);
            float o = uv - acc[j] * invM - reac;
            ((float*)&o4)[j] = fminf(fmaxf(o, 0.0f), 1.0f);
        }
        *(float4*)&out[b * IMG + iy * WW + ixb] = o4;
    }
}

// ------------------------------------------------------------------- launch
extern "C" void kernel_launch(void* const* d_in, const int* in_sizes, int n_in,
                              void* d_out, int out_size) {
    const float* u       = (const float*)d_in[0];
    const float* f       = (const float*)d_in[1];
    const float* filters = (const float*)d_in[2];
    const float* lam     = (const float*)d_in[3];
    const float* mu      = (const float*)d_in[4];
    const float* w       = (const float*)d_in[5];
    float* out = (float*)d_out;

    dim3 grid(WW / TX, HH / TY, BB);   // 3 x 15 x 8 = 360 blocks
    tnrd_kernel<<<grid, NT>>>(u, f, filters, lam, mu, w, out);
}